// round 1
// baseline (speedup 1.0000x reference)
#include <cuda_runtime.h>

// YOLO-v1 loss, fully fused single-pass reduction.
// prediction/target: (N*S*S) cells x 30 channels, fp32. Output: 1 fp32 scalar.

static constexpr int CH   = 30;   // C + 5*B
static constexpr int TILE = 256;  // cells per block
static constexpr int TPB  = 256;  // threads per block
static constexpr int PAD  = 32;   // smem row stride (conflict-free, float4-aligned)

__global__ void zero_kernel(float* out) { out[0] = 0.0f; }

__device__ __forceinline__ float iou_f(
    float ax, float ay, float aw, float ah,
    float bx, float by, float bw, float bh)
{
    float ax1 = ax - aw * 0.5f, ay1 = ay - ah * 0.5f;
    float ax2 = ax + aw * 0.5f, ay2 = ay + ah * 0.5f;
    float bx1 = bx - bw * 0.5f, by1 = by - bh * 0.5f;
    float bx2 = bx + bw * 0.5f, by2 = by + bh * 0.5f;
    float x1 = fmaxf(ax1, bx1), y1 = fmaxf(ay1, by1);
    float x2 = fminf(ax2, bx2), y2 = fminf(ay2, by2);
    float inter = fmaxf(x2 - x1, 0.0f) * fmaxf(y2 - y1, 0.0f);
    float aa = fabsf((ax2 - ax1) * (ay2 - ay1));
    float ab = fabsf((bx2 - bx1) * (by2 - by1));
    return inter / (aa + ab - inter + 1e-6f);
}

extern __shared__ float smem_dyn[];

__global__ __launch_bounds__(TPB) void yolo_loss_kernel(
    const float* __restrict__ pred, const float* __restrict__ targ,
    float* __restrict__ out, int ncells)
{
    float* ps = smem_dyn;              // TILE * PAD
    float* ts = smem_dyn + TILE * PAD; // TILE * PAD

    long base  = (long)blockIdx.x * TILE;
    int  cells = ncells - (int)base;
    if (cells > TILE) cells = TILE;

    const float* pg = pred + base * CH;
    const float* tg = targ + base * CH;

    // Coalesced staging: linear floats -> (cell, ch) with padded row stride.
    int nfl = cells * CH;
    for (int f = threadIdx.x; f < nfl; f += TPB) {
        int cell = f / CH;             // compiler -> mul-hi sequence
        int ch   = f - cell * CH;
        ps[cell * PAD + ch] = pg[f];
        ts[cell * PAD + ch] = tg[f];
    }
    __syncthreads();

    float acc = 0.0f;
    if ((int)threadIdx.x < cells) {
        const float* p = ps + threadIdx.x * PAD;
        const float* t = ts + threadIdx.x * PAD;

        float t20 = t[20];
        float iou1 = iou_f(p[21], p[22], p[23], p[24], t[21], t[22], t[23], t[24]);
        float iou2 = iou_f(p[26], p[27], p[28], p[29], t[21], t[22], t[23], t[24]);

        // bestbox selects p[29] (as written in the reference) else p[20]
        float pc = (iou2 > iou1) ? p[29] : p[20];
        float e  = t20;
        float no = 1.0f - e;

        // obj loss
        float d = e * pc - e * t20;
        acc = d * d;

        // noobj loss (two confidence channels vs t20)
        d = no * p[20] - no * t20; float nl = d * d;
        d = no * p[29] - no * t20; nl += d * d;
        acc += 0.5f * nl;

        // class loss
        float cl = 0.0f;
        #pragma unroll
        for (int k = 0; k < 20; k++) {
            float dd = e * p[k] - e * t[k];
            cl += dd * dd;
        }
        acc += cl;
        // box_loss == 0 in the reference; LAMBDA_COORD term drops out.
    }

    // warp reduce
    #pragma unroll
    for (int off = 16; off; off >>= 1)
        acc += __shfl_down_sync(0xffffffffu, acc, off);

    __shared__ float wsum[TPB / 32];
    int wid = threadIdx.x >> 5, lid = threadIdx.x & 31;
    if (lid == 0) wsum[wid] = acc;
    __syncthreads();
    if (wid == 0) {
        float v = (lid < TPB / 32) ? wsum[lid] : 0.0f;
        #pragma unroll
        for (int off = 4; off; off >>= 1)
            v += __shfl_down_sync(0xffffffffu, v, off);
        if (lid == 0) atomicAdd(out, v);
    }
}

extern "C" void kernel_launch(void* const* d_in, const int* in_sizes, int n_in,
                              void* d_out, int out_size)
{
    const float* pred = (const float*)d_in[0];
    const float* targ = (const float*)d_in[1];
    float* out = (float*)d_out;

    int ncells  = in_sizes[0] / CH;
    int nblocks = (ncells + TILE - 1) / TILE;
    size_t shmem = (size_t)(2 * TILE * PAD) * sizeof(float);  // 64 KB

    // >48KB dynamic smem opt-in. Not a stream op; latched on the correctness
    // call before capture, harmless on subsequent calls.
    cudaFuncSetAttribute(yolo_loss_kernel,
                         cudaFuncAttributeMaxDynamicSharedMemorySize, (int)shmem);

    zero_kernel<<<1, 1>>>(out);
    yolo_loss_kernel<<<nblocks, TPB, shmem>>>(pred, targ, out, ncells);
}

// round 2
// speedup vs baseline: 1.9581x; 1.9581x over previous
#include <cuda_runtime.h>

// YOLO-v1 loss, fully fused single-pass reduction.
// prediction/target: (N*S*S) cells x 30 channels, fp32. Output: 1 fp32 scalar.

static constexpr int CH   = 30;   // C + 5*B
static constexpr int TILE = 256;  // cells per block
static constexpr int TPB  = 256;  // threads per block
static constexpr int PAD  = 33;   // ODD smem row stride -> conflict-free column reads

__global__ void zero_kernel(float* out) { out[0] = 0.0f; }

__device__ __forceinline__ float iou_f(
    float ax, float ay, float aw, float ah,
    float bx, float by, float bw, float bh)
{
    float ax1 = ax - aw * 0.5f, ay1 = ay - ah * 0.5f;
    float ax2 = ax + aw * 0.5f, ay2 = ay + ah * 0.5f;
    float bx1 = bx - bw * 0.5f, by1 = by - bh * 0.5f;
    float bx2 = bx + bw * 0.5f, by2 = by + bh * 0.5f;
    float x1 = fmaxf(ax1, bx1), y1 = fmaxf(ay1, by1);
    float x2 = fminf(ax2, bx2), y2 = fminf(ay2, by2);
    float inter = fmaxf(x2 - x1, 0.0f) * fmaxf(y2 - y1, 0.0f);
    float aa = fabsf((ax2 - ax1) * (ay2 - ay1));
    float ab = fabsf((bx2 - bx1) * (by2 - by1));
    return inter / (aa + ab - inter + 1e-6f);
}

extern __shared__ float smem_dyn[];

__device__ __forceinline__ void scatter4(float* row_base, int cell, int ch, float4 v)
{
    // Store 4 consecutive channel values, handling cell-boundary wrap (CH=30).
    float vals[4] = {v.x, v.y, v.z, v.w};
    #pragma unroll
    for (int e = 0; e < 4; e++) {
        row_base[cell * PAD + ch] = vals[e];
        if (++ch == CH) { ch = 0; cell++; }
    }
}

__global__ __launch_bounds__(TPB) void yolo_loss_kernel(
    const float* __restrict__ pred, const float* __restrict__ targ,
    float* __restrict__ out, int ncells)
{
    float* ps = smem_dyn;              // TILE * PAD
    float* ts = smem_dyn + TILE * PAD; // TILE * PAD

    long base  = (long)blockIdx.x * TILE;
    int  cells = ncells - (int)base;
    if (cells > TILE) cells = TILE;

    const float* pg = pred + base * CH;
    const float* tg = targ + base * CH;

    int nfl = cells * CH;

    if ((nfl & 3) == 0) {
        // Fast path: vectorized staging. Tile base offset = TILE*CH*4 = 30720 B,
        // 16B-aligned, so float4 loads are legal.
        const float4* pg4 = reinterpret_cast<const float4*>(pg);
        const float4* tg4 = reinterpret_cast<const float4*>(tg);
        int nf4 = nfl >> 2;
        for (int q = threadIdx.x; q < nf4; q += TPB) {
            float4 pv = pg4[q];
            float4 tv = tg4[q];
            int f    = q << 2;
            int cell = f / CH;
            int ch   = f - cell * CH;
            scatter4(ps, cell, ch, pv);
            scatter4(ts, cell, ch, tv);
        }
    } else {
        for (int f = threadIdx.x; f < nfl; f += TPB) {
            int cell = f / CH;
            int ch   = f - cell * CH;
            ps[cell * PAD + ch] = pg[f];
            ts[cell * PAD + ch] = tg[f];
        }
    }
    __syncthreads();

    float acc = 0.0f;
    if ((int)threadIdx.x < cells) {
        const float* p = ps + threadIdx.x * PAD;
        const float* t = ts + threadIdx.x * PAD;

        float t20 = t[20];
        float iou1 = iou_f(p[21], p[22], p[23], p[24], t[21], t[22], t[23], t[24]);
        float iou2 = iou_f(p[26], p[27], p[28], p[29], t[21], t[22], t[23], t[24]);

        // bestbox selects p[29] (as written in the reference) else p[20]
        float pc = (iou2 > iou1) ? p[29] : p[20];
        float e  = t20;
        float no = 1.0f - e;

        // obj loss
        float d = e * pc - e * t20;
        acc = d * d;

        // noobj loss (two confidence channels vs t20), weight 0.5
        d = no * p[20] - no * t20; float nl = d * d;
        d = no * p[29] - no * t20; nl += d * d;
        acc += 0.5f * nl;

        // class loss
        float cl = 0.0f;
        #pragma unroll
        for (int k = 0; k < 20; k++) {
            float dd = e * p[k] - e * t[k];
            cl += dd * dd;
        }
        acc += cl;
        // box_loss == 0 in the reference; LAMBDA_COORD term drops out.
    }

    // warp reduce
    #pragma unroll
    for (int off = 16; off; off >>= 1)
        acc += __shfl_down_sync(0xffffffffu, acc, off);

    __shared__ float wsum[TPB / 32];
    int wid = threadIdx.x >> 5, lid = threadIdx.x & 31;
    if (lid == 0) wsum[wid] = acc;
    __syncthreads();
    if (wid == 0) {
        float v = (lid < TPB / 32) ? wsum[lid] : 0.0f;
        #pragma unroll
        for (int off = 4; off; off >>= 1)
            v += __shfl_down_sync(0xffffffffu, v, off);
        if (lid == 0) atomicAdd(out, v);
    }
}

extern "C" void kernel_launch(void* const* d_in, const int* in_sizes, int n_in,
                              void* d_out, int out_size)
{
    const float* pred = (const float*)d_in[0];
    const float* targ = (const float*)d_in[1];
    float* out = (float*)d_out;

    int ncells  = in_sizes[0] / CH;
    int nblocks = (ncells + TILE - 1) / TILE;
    size_t shmem = (size_t)(2 * TILE * PAD) * sizeof(float);  // 67584 B

    cudaFuncSetAttribute(yolo_loss_kernel,
                         cudaFuncAttributeMaxDynamicSharedMemorySize, (int)shmem);

    zero_kernel<<<1, 1>>>(out);
    yolo_loss_kernel<<<nblocks, TPB, shmem>>>(pred, targ, out, ncells);
}

// round 3
// speedup vs baseline: 2.3483x; 1.1993x over previous
#include <cuda_runtime.h>

// YOLO-v1 loss, fully fused single-pass reduction.
// prediction/target: (N*S*S) cells x 30 channels, fp32. Output: 1 fp32 scalar.
//
// R3: raw-layout SMEM staging (straight float4 copy, STS.128) instead of
// de-interleaved scatter. Compute reads stride-30 rows from SMEM (2-way
// bank conflict only, since gcd(30,32)=2).

static constexpr int CH   = 30;   // C + 5*B
static constexpr int TILE = 256;  // cells per block
static constexpr int TPB  = 256;  // threads per block

__global__ void zero_kernel(float* out) { out[0] = 0.0f; }

__device__ __forceinline__ float iou_f(
    float ax, float ay, float aw, float ah,
    float bx, float by, float bw, float bh)
{
    float ax1 = ax - aw * 0.5f, ay1 = ay - ah * 0.5f;
    float ax2 = ax + aw * 0.5f, ay2 = ay + ah * 0.5f;
    float bx1 = bx - bw * 0.5f, by1 = by - bh * 0.5f;
    float bx2 = bx + bw * 0.5f, by2 = by + bh * 0.5f;
    float x1 = fmaxf(ax1, bx1), y1 = fmaxf(ay1, by1);
    float x2 = fminf(ax2, bx2), y2 = fminf(ay2, by2);
    float inter = fmaxf(x2 - x1, 0.0f) * fmaxf(y2 - y1, 0.0f);
    float aa = fabsf((ax2 - ax1) * (ay2 - ay1));
    float ab = fabsf((bx2 - bx1) * (by2 - by1));
    return inter / (aa + ab - inter + 1e-6f);
}

extern __shared__ float smem_dyn[];

__global__ __launch_bounds__(TPB) void yolo_loss_kernel(
    const float* __restrict__ pred, const float* __restrict__ targ,
    float* __restrict__ out, int ncells)
{
    float* ps = smem_dyn;             // TILE*CH floats, raw cell-major layout
    float* ts = smem_dyn + TILE * CH;

    long base  = (long)blockIdx.x * TILE;
    int  cells = ncells - (int)base;
    if (cells > TILE) cells = TILE;

    const float* pg = pred + base * CH;
    const float* tg = targ + base * CH;

    int nfl = cells * CH;

    if ((nfl & 3) == 0) {
        // Straight vectorized copy: global float4 -> smem float4, same order.
        // Tile base offset = TILE*CH*4 B = 30720 B (16B aligned).
        const float4* __restrict__ pg4 = reinterpret_cast<const float4*>(pg);
        const float4* __restrict__ tg4 = reinterpret_cast<const float4*>(tg);
        float4* ps4 = reinterpret_cast<float4*>(ps);
        float4* ts4 = reinterpret_cast<float4*>(ts);
        int nf4 = nfl >> 2;  // 1920 for a full tile
        #pragma unroll 4
        for (int q = threadIdx.x; q < nf4; q += TPB) {
            ps4[q] = pg4[q];
            ts4[q] = tg4[q];
        }
    } else {
        for (int f = threadIdx.x; f < nfl; f += TPB) {
            ps[f] = pg[f];
            ts[f] = tg[f];
        }
    }
    __syncthreads();

    float acc = 0.0f;
    if ((int)threadIdx.x < cells) {
        const float* __restrict__ p = ps + threadIdx.x * CH;
        const float* __restrict__ t = ts + threadIdx.x * CH;

        float t20 = t[20];
        float t21 = t[21], t22 = t[22], t23 = t[23], t24 = t[24];
        float iou1 = iou_f(p[21], p[22], p[23], p[24], t21, t22, t23, t24);
        float iou2 = iou_f(p[26], p[27], p[28], p[29], t21, t22, t23, t24);

        // bestbox selects p[29] (as written in the reference) else p[20]
        float pc = (iou2 > iou1) ? p[29] : p[20];
        float e  = t20;
        float no = 1.0f - e;

        // obj loss
        float d = e * pc - e * t20;
        acc = d * d;

        // noobj loss (two confidence channels vs t20), weight 0.5
        d = no * p[20] - no * t20; float nl = d * d;
        d = no * p[29] - no * t20; nl += d * d;
        acc += 0.5f * nl;

        // class loss
        float cl = 0.0f;
        #pragma unroll
        for (int k = 0; k < 20; k++) {
            float dd = e * p[k] - e * t[k];
            cl += dd * dd;
        }
        acc += cl;
        // box_loss == 0 in the reference; LAMBDA_COORD term drops out.
    }

    // warp reduce
    #pragma unroll
    for (int off = 16; off; off >>= 1)
        acc += __shfl_down_sync(0xffffffffu, acc, off);

    __shared__ float wsum[TPB / 32];
    int wid = threadIdx.x >> 5, lid = threadIdx.x & 31;
    if (lid == 0) wsum[wid] = acc;
    __syncthreads();
    if (wid == 0) {
        float v = (lid < TPB / 32) ? wsum[lid] : 0.0f;
        #pragma unroll
        for (int off = 4; off; off >>= 1)
            v += __shfl_down_sync(0xffffffffu, v, off);
        if (lid == 0) atomicAdd(out, v);
    }
}

extern "C" void kernel_launch(void* const* d_in, const int* in_sizes, int n_in,
                              void* d_out, int out_size)
{
    const float* pred = (const float*)d_in[0];
    const float* targ = (const float*)d_in[1];
    float* out = (float*)d_out;

    int ncells  = in_sizes[0] / CH;
    int nblocks = (ncells + TILE - 1) / TILE;
    size_t shmem = (size_t)(2 * TILE * CH) * sizeof(float);  // 61440 B

    cudaFuncSetAttribute(yolo_loss_kernel,
                         cudaFuncAttributeMaxDynamicSharedMemorySize, (int)shmem);

    zero_kernel<<<1, 1>>>(out);
    yolo_loss_kernel<<<nblocks, TPB, shmem>>>(pred, targ, out, ncells);
}

// round 4
// speedup vs baseline: 2.6954x; 1.1478x over previous
#include <cuda_runtime.h>
#include <cstdint>

// YOLO-v1 loss, fused single-pass reduction.
// R4: persistent CTAs + cp.async (LDGSTS) double-buffered pipeline.
// Each CTA streams tiles of 128 cells; prefetches tile n+1 while computing n.

static constexpr int CH   = 30;   // C + 5*B
static constexpr int TILE = 128;  // cells per pipeline stage
static constexpr int TPB  = 256;  // threads per block
static constexpr int NF4  = TILE * CH / 4;       // 960 float4 per tensor-stage
static constexpr int STAGE_FLOATS = TILE * CH;   // 3840
static constexpr int GRID = 456;  // 152 SMs * 3 CTAs

__global__ void zero_kernel(float* out) { out[0] = 0.0f; }

__device__ __forceinline__ void cp16(float4* smem, const float4* gmem) {
    uint32_t s = (uint32_t)__cvta_generic_to_shared(smem);
    asm volatile("cp.async.cg.shared.global [%0], [%1], 16;\n" :: "r"(s), "l"(gmem));
}
__device__ __forceinline__ void cp_commit() {
    asm volatile("cp.async.commit_group;\n" ::: "memory");
}
__device__ __forceinline__ void cp_wait1() {
    asm volatile("cp.async.wait_group 1;\n" ::: "memory");
}

__device__ __forceinline__ float iou_f(
    float ax, float ay, float aw, float ah,
    float bx, float by, float bw, float bh)
{
    float ax1 = ax - aw * 0.5f, ay1 = ay - ah * 0.5f;
    float ax2 = ax + aw * 0.5f, ay2 = ay + ah * 0.5f;
    float bx1 = bx - bw * 0.5f, by1 = by - bh * 0.5f;
    float bx2 = bx + bw * 0.5f, by2 = by + bh * 0.5f;
    float x1 = fmaxf(ax1, bx1), y1 = fmaxf(ay1, by1);
    float x2 = fminf(ax2, bx2), y2 = fminf(ay2, by2);
    float inter = fmaxf(x2 - x1, 0.0f) * fmaxf(y2 - y1, 0.0f);
    float aa = fabsf((ax2 - ax1) * (ay2 - ay1));
    float ab = fabsf((bx2 - bx1) * (by2 - by1));
    return inter / (aa + ab - inter + 1e-6f);
}

extern __shared__ float smem_dyn[];  // [2 stages][2 tensors][STAGE_FLOATS]

// Prefetch one tile (pred+targ) into the given stage buffers via cp.async.
__device__ __forceinline__ void prefetch_tile(
    const float* __restrict__ pred, const float* __restrict__ targ,
    float* pbuf, float* tbuf, long tile, int ncells)
{
    long cbase = tile * TILE;
    int  cells = ncells - (int)cbase;
    if (cells > TILE) cells = TILE;
    int nfl = cells * CH;
    const float* pg = pred + cbase * CH;
    const float* tg = targ + cbase * CH;

    int nf4 = nfl >> 2;
    const float4* pg4 = reinterpret_cast<const float4*>(pg);
    const float4* tg4 = reinterpret_cast<const float4*>(tg);
    float4* pb4 = reinterpret_cast<float4*>(pbuf);
    float4* tb4 = reinterpret_cast<float4*>(tbuf);
    for (int q = threadIdx.x; q < nf4; q += TPB) {
        cp16(&pb4[q], &pg4[q]);
        cp16(&tb4[q], &tg4[q]);
    }
    // scalar tail (only possible on the very last tile for odd shapes)
    for (int f = (nf4 << 2) + threadIdx.x; f < nfl; f += TPB) {
        pbuf[f] = pg[f];
        tbuf[f] = tg[f];
    }
}

__device__ __forceinline__ float compute_tile(
    const float* __restrict__ pbuf, const float* __restrict__ tbuf,
    long tile, int ncells)
{
    long cbase = tile * TILE;
    int  cells = ncells - (int)cbase;
    if (cells > TILE) cells = TILE;
    if ((int)threadIdx.x >= cells) return 0.0f;

    const float* p = pbuf + threadIdx.x * CH;
    const float* t = tbuf + threadIdx.x * CH;

    float t20 = t[20];
    float t21 = t[21], t22 = t[22], t23 = t[23], t24 = t[24];
    float iou1 = iou_f(p[21], p[22], p[23], p[24], t21, t22, t23, t24);
    float iou2 = iou_f(p[26], p[27], p[28], p[29], t21, t22, t23, t24);

    // bestbox selects p[29] (as written in the reference) else p[20]
    float pc = (iou2 > iou1) ? p[29] : p[20];
    float e  = t20;
    float no = 1.0f - e;

    float d = e * pc - e * t20;          // obj loss
    float acc = d * d;

    d = no * p[20] - no * t20; float nl = d * d;   // noobj (x0.5)
    d = no * p[29] - no * t20; nl += d * d;
    acc += 0.5f * nl;

    float cl = 0.0f;                      // class loss
    #pragma unroll
    for (int k = 0; k < 20; k++) {
        float dd = e * p[k] - e * t[k];
        cl += dd * dd;
    }
    acc += cl;
    // box_loss == 0 in the reference; LAMBDA_COORD term drops out.
    return acc;
}

__global__ __launch_bounds__(TPB) void yolo_loss_kernel(
    const float* __restrict__ pred, const float* __restrict__ targ,
    float* __restrict__ out, int ncells, int ntiles)
{
    float* buf[2][2];
    buf[0][0] = smem_dyn;                     // stage0 pred
    buf[0][1] = smem_dyn + STAGE_FLOATS;      // stage0 targ
    buf[1][0] = smem_dyn + 2 * STAGE_FLOATS;  // stage1 pred
    buf[1][1] = smem_dyn + 3 * STAGE_FLOATS;  // stage1 targ

    float acc = 0.0f;

    long tile = blockIdx.x;
    if (tile < ntiles)
        prefetch_tile(pred, targ, buf[0][0], buf[0][1], tile, ncells);
    cp_commit();

    int it = 0;
    for (; tile < ntiles; tile += gridDim.x, it++) {
        long nextTile = tile + gridDim.x;
        int  nb = (it + 1) & 1;
        if (nextTile < ntiles)
            prefetch_tile(pred, targ, buf[nb][0], buf[nb][1], nextTile, ncells);
        cp_commit();
        cp_wait1();          // current tile's group done; next may be in flight
        __syncthreads();     // all stages' data visible to all threads

        int cb = it & 1;
        acc += compute_tile(buf[cb][0], buf[cb][1], tile, ncells);

        __syncthreads();     // done reading before buffer cb is refilled
    }

    // final reduction: warp shuffle -> block -> one atomic per block
    #pragma unroll
    for (int off = 16; off; off >>= 1)
        acc += __shfl_down_sync(0xffffffffu, acc, off);

    __shared__ float wsum[TPB / 32];
    int wid = threadIdx.x >> 5, lid = threadIdx.x & 31;
    if (lid == 0) wsum[wid] = acc;
    __syncthreads();
    if (wid == 0) {
        float v = (lid < TPB / 32) ? wsum[lid] : 0.0f;
        #pragma unroll
        for (int off = 4; off; off >>= 1)
            v += __shfl_down_sync(0xffffffffu, v, off);
        if (lid == 0) atomicAdd(out, v);
    }
}

extern "C" void kernel_launch(void* const* d_in, const int* in_sizes, int n_in,
                              void* d_out, int out_size)
{
    const float* pred = (const float*)d_in[0];
    const float* targ = (const float*)d_in[1];
    float* out = (float*)d_out;

    int ncells = in_sizes[0] / CH;
    int ntiles = (ncells + TILE - 1) / TILE;
    size_t shmem = (size_t)(4 * STAGE_FLOATS) * sizeof(float);  // 61440 B

    cudaFuncSetAttribute(yolo_loss_kernel,
                         cudaFuncAttributeMaxDynamicSharedMemorySize, (int)shmem);

    int nblocks = GRID < ntiles ? GRID : ntiles;
    zero_kernel<<<1, 1>>>(out);
    yolo_loss_kernel<<<nblocks, TPB, shmem>>>(pred, targ, out, ncells, ntiles);
}

// round 10
// speedup vs baseline: 2.7924x; 1.0360x over previous
#include <cuda_runtime.h>
#include <cstdint>

// YOLO-v1 loss, fused single-pass reduction.
// R5 (re-run after infra failure): persistent CTAs + cp.async 3-stage
// pipeline, ONE barrier per tile.
// Order per iter: wait(oldest) -> sync -> compute(t_i) -> prefetch(t_{i+2}).
// Stage s=(it+2)%3 being refilled was last READ at iter it-1; that read
// happens-before the sync at iter it's top, which happens-before this
// prefetch -> safe with a single barrier.

static constexpr int CH   = 30;   // C + 5*B
static constexpr int TILE = 128;  // cells per pipeline stage
static constexpr int TPB  = 256;  // threads per block
static constexpr int STAGE_FLOATS = TILE * CH;   // 3840 floats per tensor-stage
static constexpr int NSTAGE = 3;
static constexpr int GRID = 304;  // 152 SMs * 2 resident CTAs (92KB smem each)

__global__ void zero_kernel(float* out) { out[0] = 0.0f; }

__device__ __forceinline__ void cp16(float4* smem, const float4* gmem) {
    uint32_t s = (uint32_t)__cvta_generic_to_shared(smem);
    asm volatile("cp.async.cg.shared.global [%0], [%1], 16;\n" :: "r"(s), "l"(gmem));
}
__device__ __forceinline__ void cp_commit() {
    asm volatile("cp.async.commit_group;\n" ::: "memory");
}
__device__ __forceinline__ void cp_wait1() {   // block until <=1 group pending
    asm volatile("cp.async.wait_group 1;\n" ::: "memory");
}

__device__ __forceinline__ float iou_f(
    float ax, float ay, float aw, float ah,
    float bx, float by, float bw, float bh)
{
    float ax1 = ax - aw * 0.5f, ay1 = ay - ah * 0.5f;
    float ax2 = ax + aw * 0.5f, ay2 = ay + ah * 0.5f;
    float bx1 = bx - bw * 0.5f, by1 = by - bh * 0.5f;
    float bx2 = bx + bw * 0.5f, by2 = by + bh * 0.5f;
    float x1 = fmaxf(ax1, bx1), y1 = fmaxf(ay1, by1);
    float x2 = fminf(ax2, bx2), y2 = fminf(ay2, by2);
    float inter = fmaxf(x2 - x1, 0.0f) * fmaxf(y2 - y1, 0.0f);
    float aa = fabsf((ax2 - ax1) * (ay2 - ay1));
    float ab = fabsf((bx2 - bx1) * (by2 - by1));
    return inter / (aa + ab - inter + 1e-6f);
}

extern __shared__ float smem_dyn[];  // [NSTAGE][2 tensors][STAGE_FLOATS]

__device__ __forceinline__ void prefetch_tile(
    const float* __restrict__ pred, const float* __restrict__ targ,
    float* pbuf, float* tbuf, long tile, int ncells)
{
    long cbase = tile * TILE;
    int  cells = ncells - (int)cbase;
    if (cells > TILE) cells = TILE;
    int nfl = cells * CH;
    const float* pg = pred + cbase * CH;
    const float* tg = targ + cbase * CH;

    int nf4 = nfl >> 2;
    const float4* pg4 = reinterpret_cast<const float4*>(pg);
    const float4* tg4 = reinterpret_cast<const float4*>(tg);
    float4* pb4 = reinterpret_cast<float4*>(pbuf);
    float4* tb4 = reinterpret_cast<float4*>(tbuf);
    for (int q = threadIdx.x; q < nf4; q += TPB) {
        cp16(&pb4[q], &pg4[q]);
        cp16(&tb4[q], &tg4[q]);
    }
    for (int f = (nf4 << 2) + threadIdx.x; f < nfl; f += TPB) {  // odd tail
        pbuf[f] = pg[f];
        tbuf[f] = tg[f];
    }
}

__device__ __forceinline__ float compute_tile(
    const float* __restrict__ pbuf, const float* __restrict__ tbuf,
    long tile, int ncells)
{
    long cbase = tile * TILE;
    int  cells = ncells - (int)cbase;
    if (cells > TILE) cells = TILE;
    if ((int)threadIdx.x >= cells) return 0.0f;

    const float* p = pbuf + threadIdx.x * CH;
    const float* t = tbuf + threadIdx.x * CH;

    float t20 = t[20];
    float t21 = t[21], t22 = t[22], t23 = t[23], t24 = t[24];
    float iou1 = iou_f(p[21], p[22], p[23], p[24], t21, t22, t23, t24);
    float iou2 = iou_f(p[26], p[27], p[28], p[29], t21, t22, t23, t24);

    // bestbox selects p[29] (as written in the reference) else p[20]
    float pc = (iou2 > iou1) ? p[29] : p[20];
    float e  = t20;
    float no = 1.0f - e;

    float d = e * pc - e * t20;          // obj loss
    float acc = d * d;

    d = no * p[20] - no * t20; float nl = d * d;   // noobj (x0.5)
    d = no * p[29] - no * t20; nl += d * d;
    acc += 0.5f * nl;

    float cl = 0.0f;                      // class loss
    #pragma unroll
    for (int k = 0; k < 20; k++) {
        float dd = e * p[k] - e * t[k];
        cl += dd * dd;
    }
    acc += cl;
    // box_loss == 0 in the reference; LAMBDA_COORD term drops out.
    return acc;
}

__global__ __launch_bounds__(TPB) void yolo_loss_kernel(
    const float* __restrict__ pred, const float* __restrict__ targ,
    float* __restrict__ out, int ncells, int ntiles)
{
    float* pb[NSTAGE];
    float* tb[NSTAGE];
    #pragma unroll
    for (int s = 0; s < NSTAGE; s++) {
        pb[s] = smem_dyn + (2 * s)     * STAGE_FLOATS;
        tb[s] = smem_dyn + (2 * s + 1) * STAGE_FLOATS;
    }

    float acc = 0.0f;

    // Prologue: prefetch tiles t0, t1 into stages 0, 1.
    long t0 = blockIdx.x;
    long t1 = t0 + gridDim.x;
    if (t0 < ntiles) prefetch_tile(pred, targ, pb[0], tb[0], t0, ncells);
    cp_commit();
    if (t1 < ntiles) prefetch_tile(pred, targ, pb[1], tb[1], t1, ncells);
    cp_commit();

    int it = 0;
    for (long tile = t0; tile < ntiles; tile += gridDim.x, it++) {
        cp_wait1();          // oldest pending group (this tile) complete
        __syncthreads();     // all threads' copies visible; also orders reuse

        int s = it % NSTAGE;
        acc += compute_tile(pb[s], tb[s], tile, ncells);

        long nxt = tile + 2L * gridDim.x;
        int  ns  = (it + 2) % NSTAGE;
        if (nxt < ntiles)
            prefetch_tile(pred, targ, pb[ns], tb[ns], nxt, ncells);
        cp_commit();         // commit even if empty: keeps group accounting fixed
    }

    // final reduction: warp shuffle -> block -> one atomic per block
    #pragma unroll
    for (int off = 16; off; off >>= 1)
        acc += __shfl_down_sync(0xffffffffu, acc, off);

    __shared__ float wsum[TPB / 32];
    int wid = threadIdx.x >> 5, lid = threadIdx.x & 31;
    if (lid == 0) wsum[wid] = acc;
    __syncthreads();
    if (wid == 0) {
        float v = (lid < TPB / 32) ? wsum[lid] : 0.0f;
        #pragma unroll
        for (int off = 4; off; off >>= 1)
            v += __shfl_down_sync(0xffffffffu, v, off);
        if (lid == 0) atomicAdd(out, v);
    }
}

extern "C" void kernel_launch(void* const* d_in, const int* in_sizes, int n_in,
                              void* d_out, int out_size)
{
    const float* pred = (const float*)d_in[0];
    const float* targ = (const float*)d_in[1];
    float* out = (float*)d_out;

    int ncells = in_sizes[0] / CH;
    int ntiles = (ncells + TILE - 1) / TILE;
    size_t shmem = (size_t)(2 * NSTAGE * STAGE_FLOATS) * sizeof(float); // 92160 B

    cudaFuncSetAttribute(yolo_loss_kernel,
                         cudaFuncAttributeMaxDynamicSharedMemorySize, (int)shmem);

    int nblocks = GRID < ntiles ? GRID : ntiles;
    zero_kernel<<<1, 1>>>(out);
    yolo_loss_kernel<<<nblocks, TPB, shmem>>>(pred, targ, out, ncells, ntiles);
}